// round 13
// baseline (speedup 1.0000x reference)
#include <cuda_runtime.h>
#include <cuda_bf16.h>
#include <math.h>

// Problem constants
#define B_  64
#define T_  2048
#define O_  3
#define D_  512
#define M_  100000u
#define H_  4

// Tiling
#define NCH 8            // chunks of T per batch row
#define TCH (T_ / NCH)   // 256 timesteps per chunk
#define TW  8            // unmasked timesteps per tile
#define NT  128          // thread t owns dims [4t,4t+4); warp == head

// Chunk partial softmax state
__device__ float g_m[B_ * NCH * H_];
__device__ float g_s[B_ * NCH * H_];
__device__ float g_acc[B_ * NCH * D_];

__global__ __launch_bounds__(NT, 3)
void pass1_kernel(const int* __restrict__ tok,
                  const int* __restrict__ prv,
                  const int* __restrict__ mask,       // bool delivered as int32
                  const float* __restrict__ embed,
                  const float* __restrict__ engram,
                  const float* __restrict__ gate_logit,
                  const float* __restrict__ temp,
                  const float* __restrict__ salW,
                  const float* __restrict__ salb)
{
    const int b = blockIdx.y;
    const int c = blockIdx.x;
    const int t = threadIdx.x;          // 0..127
    const int h = t >> 5;               // warp index == head
    const int lane = t & 31;

    __shared__ unsigned int   stok[TCH + O_];
    __shared__ unsigned short sidx[TCH + 3 * TW];   // compacted unmasked local-t list
    __shared__ float spart[2][TW][H_][H_];          // [parity][j][warp][head]
    __shared__ int   scnt[8], sbase[8], snv;

    const int t0 = c * TCH;

    // Stage tokens
    for (int i = t; i < TCH + O_; i += NT) {
        int u = t0 - O_ + i;
        stok[i] = (u < 0) ? (unsigned)prv[b * O_ + (O_ + u)]
                          : (unsigned)tok[b * T_ + u];
    }

    // ---- Mask compaction: ballot + scan ----
    unsigned bal[2]; int mv[2];
    #pragma unroll
    for (int k = 0; k < 2; k++) {
        int seg = h * 2 + k;                       // warp h owns segments 2h, 2h+1
        mv[k]  = (mask[b * T_ + t0 + seg * 32 + lane] != 0);
        bal[k] = __ballot_sync(0xffffffffu, mv[k]);
        if (lane == 0) scnt[seg] = __popc(bal[k]);
    }
    __syncthreads();
    if (t == 0) {
        int run = 0;
        #pragma unroll
        for (int seg = 0; seg < 8; seg++) { sbase[seg] = run; run += scnt[seg]; }
        snv = run;
    }
    __syncthreads();
    #pragma unroll
    for (int k = 0; k < 2; k++) {
        int seg = h * 2 + k;
        int off = sbase[seg] + __popc(bal[k] & ((1u << lane) - 1u));
        if (mv[k]) sidx[off] = (unsigned short)(seg * 32 + lane);
    }
    const int nv = snv;
    // pad safely (loads may run ahead up to 3 tiles)
    for (int i = nv + t; i < nv + 3 * TW; i += NT) sidx[i] = 0;
    __syncthreads();

    // Per-thread constants
    float4 gl = __ldg((const float4*)gate_logit + t);
    float4 g4;
    g4.x = 1.0f / (1.0f + __expf(-gl.x));
    g4.y = 1.0f / (1.0f + __expf(-gl.y));
    g4.z = 1.0f / (1.0f + __expf(-gl.z));
    g4.w = 1.0f / (1.0f + __expf(-gl.w));

    float4 Wr0 = __ldg((const float4*)salW + (t * 4 + 0));
    float4 Wr1 = __ldg((const float4*)salW + (t * 4 + 1));
    float4 Wr2 = __ldg((const float4*)salW + (t * 4 + 2));
    float4 Wr3 = __ldg((const float4*)salW + (t * 4 + 3));

    const float invT = 1.0f / (log1pf(__expf(temp[h])) + 0.3f);
    const float bias = salb[h];

    unsigned P0, P1, P2, P3;
    {
        unsigned x = 131u + (unsigned)h * 1009u;
        P0 = x; x = x * 31u + 1u;
        P1 = x; x = x * 31u + 1u;
        P2 = x; x = x * 31u + 1u;
        P3 = x;
    }

    float  m = -1e30f, s = 0.0f;
    float4 acc = make_float4(0.f, 0.f, 0.f, 0.f);

#define LOAD_TILE(TT, E, BV)                                                   \
    do {                                                                       \
        _Pragma("unroll")                                                      \
        for (int j = 0; j < TW; j++) {                                         \
            int li = sidx[(TT) + j];                                           \
            unsigned c0 = stok[li + 3];                                        \
            unsigned c1 = stok[li + 2];                                        \
            unsigned c2 = stok[li + 1];                                        \
            unsigned c3 = stok[li + 0];                                        \
            unsigned idx = (c0 * P0 + c1 * P1 + c2 * P2 + c3 * P3) % M_;       \
            E[j]  = __ldcg((const float4*)(engram + (size_t)idx * D_) + t);    \
            BV[j] = __ldg ((const float4*)(embed  + (size_t)c0  * D_) + t);    \
        }                                                                      \
    } while (0)

#define COMPUTE_TILE(TT, E, BV)                                                \
    do {                                                                       \
        const int pb = ((TT) / TW) & 1;                                        \
        _Pragma("unroll")                                                      \
        for (int j = 0; j < TW; j++) {                                         \
            float4 x4;                                                         \
            x4.x = fmaf(E[j].x, g4.x, BV[j].x);                                \
            x4.y = fmaf(E[j].y, g4.y, BV[j].y);                                \
            x4.z = fmaf(E[j].z, g4.z, BV[j].z);                                \
            x4.w = fmaf(E[j].w, g4.w, BV[j].w);                                \
            E[j] = x4;                                                         \
            float p0 = fmaf(x4.x, Wr0.x, fmaf(x4.y, Wr1.x, fmaf(x4.z, Wr2.x, x4.w * Wr3.x))); \
            float p1 = fmaf(x4.x, Wr0.y, fmaf(x4.y, Wr1.y, fmaf(x4.z, Wr2.y, x4.w * Wr3.y))); \
            float p2 = fmaf(x4.x, Wr0.z, fmaf(x4.y, Wr1.z, fmaf(x4.z, Wr2.z, x4.w * Wr3.z))); \
            float p3 = fmaf(x4.x, Wr0.w, fmaf(x4.y, Wr1.w, fmaf(x4.z, Wr2.w, x4.w * Wr3.w))); \
            p0 += __shfl_xor_sync(0xffffffffu, p0, 16);                        \
            p1 += __shfl_xor_sync(0xffffffffu, p1, 16);                        \
            p2 += __shfl_xor_sync(0xffffffffu, p2, 16);                        \
            p3 += __shfl_xor_sync(0xffffffffu, p3, 16);                        \
            p0 += __shfl_xor_sync(0xffffffffu, p0, 8);                         \
            p1 += __shfl_xor_sync(0xffffffffu, p1, 8);                         \
            p2 += __shfl_xor_sync(0xffffffffu, p2, 8);                         \
            p3 += __shfl_xor_sync(0xffffffffu, p3, 8);                         \
            int oct = lane >> 3;                                               \
            float v = (oct == 0) ? p0 : (oct == 1) ? p1 : (oct == 2) ? p2 : p3;\
            v += __shfl_xor_sync(0xffffffffu, v, 4);                           \
            v += __shfl_xor_sync(0xffffffffu, v, 2);                           \
            v += __shfl_xor_sync(0xffffffffu, v, 1);                           \
            if ((lane & 7) == 0) spart[pb][j][h][oct] = v;                     \
        }                                                                      \
        __syncthreads();                                                       \
        float l[TW]; float lm = -3e38f;                                        \
        _Pragma("unroll")                                                      \
        for (int j = 0; j < TW; j++) {                                         \
            float lg = spart[pb][j][0][h] + spart[pb][j][1][h]                 \
                     + spart[pb][j][2][h] + spart[pb][j][3][h];                \
            l[j] = ((TT) + j < nv) ? (lg + bias) * invT : -3e38f;              \
            lm = fmaxf(lm, l[j]);                                              \
        }                                                                      \
        float nm = fmaxf(m, lm);                                               \
        float sc = __expf(m - nm);                                             \
        float ws = 0.0f; float w[TW];                                          \
        _Pragma("unroll")                                                      \
        for (int j = 0; j < TW; j++) {                                         \
            w[j] = ((TT) + j < nv) ? __expf(l[j] - nm) : 0.0f;                 \
            ws += w[j];                                                        \
        }                                                                      \
        s = fmaf(s, sc, ws);                                                   \
        float ax = acc.x * sc, ay = acc.y * sc, az = acc.z * sc, aw = acc.w * sc; \
        _Pragma("unroll")                                                      \
        for (int j = 0; j < TW; j++) {                                         \
            ax = fmaf(w[j], E[j].x, ax);                                       \
            ay = fmaf(w[j], E[j].y, ay);                                       \
            az = fmaf(w[j], E[j].z, az);                                       \
            aw = fmaf(w[j], E[j].w, aw);                                       \
        }                                                                      \
        acc.x = ax; acc.y = ay; acc.z = az; acc.w = aw;                        \
        m = nm;                                                                \
    } while (0)

    if (nv > 0) {
        const int nvr = ((nv + 2 * TW - 1) / (2 * TW)) * (2 * TW);
        float4 eA[TW], bvA[TW], eB[TW], bvB[TW];
        LOAD_TILE(0, eA, bvA);
        for (int tt = 0; tt < nvr; tt += 2 * TW) {
            LOAD_TILE(tt + TW, eB, bvB);
            COMPUTE_TILE(tt, eA, bvA);
            LOAD_TILE(tt + 2 * TW, eA, bvA);
            COMPUTE_TILE(tt + TW, eB, bvB);
        }
    }

    const int pi = (b * NCH + c);
    ((float4*)(g_acc + (size_t)pi * D_))[t] = acc;
    if (lane == 0) {
        g_m[pi * H_ + h] = m;
        g_s[pi * H_ + h] = s;
    }
#undef LOAD_TILE
#undef COMPUTE_TILE
}

__global__ __launch_bounds__(512)
void pass2_kernel(const float* __restrict__ gateW,
                  const float* __restrict__ gateb,
                  const float* __restrict__ rms_scale,
                  float* __restrict__ out)
{
    const int b = blockIdx.x;
    const int d = threadIdx.x;
    const int h = d >> 7;
    const int ld = d & 127;
    const int lane = d & 31;
    const int wid  = d >> 5;

    __shared__ float red_g[16];
    __shared__ float red_q[16];
    __shared__ float sgl[H_];
    __shared__ float ssq_sh;

    float m = -1e30f;
    #pragma unroll
    for (int c = 0; c < NCH; c++)
        m = fmaxf(m, g_m[(b * NCH + c) * H_ + h]);
    float s = 0.0f, a = 0.0f;
    #pragma unroll
    for (int c = 0; c < NCH; c++) {
        float mc = g_m[(b * NCH + c) * H_ + h];
        float sc = __expf(mc - m);
        s += g_s[(b * NCH + c) * H_ + h] * sc;
        a += g_acc[(b * NCH + c) * D_ + d] * sc;
    }
    float wv = a / (s + 1e-6f);

    float p = wv * gateW[ld];
    #pragma unroll
    for (int o = 16; o > 0; o >>= 1) p += __shfl_xor_sync(0xffffffffu, p, o);
    if (lane == 0) red_g[wid] = p;

    float q = wv * wv;
    #pragma unroll
    for (int o = 16; o > 0; o >>= 1) q += __shfl_xor_sync(0xffffffffu, q, o);
    if (lane == 0) red_q[wid] = q;
    __syncthreads();

    if (d < H_) {
        sgl[d] = red_g[d * 4] + red_g[d * 4 + 1] + red_g[d * 4 + 2] + red_g[d * 4 + 3] + gateb[0];
    }
    if (d == 0) {
        float qq = 0.0f;
        #pragma unroll
        for (int i = 0; i < 16; i++) qq += red_q[i];
        ssq_sh = qq;
    }
    __syncthreads();

    float valid = (s > 0.0f) ? 1.0f : 0.0f;
    float u = valid / (1.0f + __expf(-sgl[h]));
    float rms = sqrtf(ssq_sh * (1.0f / (float)D_) + 1e-6f);

    out[b * (2 * D_) + d]       = wv / rms * rms_scale[d];
    out[b * (2 * D_) + D_ + d]  = u;
}

// Profiler consistently captures absolute launch #3 (0-based). Three minimal
// nops put pass1 there. Remove once pass1 is characterized.
__global__ void nop_kernel() {}

extern "C" void kernel_launch(void* const* d_in, const int* in_sizes, int n_in,
                              void* d_out, int out_size)
{
    const int*   tok        = (const int*)d_in[0];
    const int*   prv        = (const int*)d_in[1];
    const int*   mask       = (const int*)d_in[2];
    const float* embed      = (const float*)d_in[3];
    const float* engram     = (const float*)d_in[4];
    const float* gate_logit = (const float*)d_in[5];
    const float* temp       = (const float*)d_in[6];
    const float* salW       = (const float*)d_in[7];
    const float* salb       = (const float*)d_in[8];
    const float* gateW      = (const float*)d_in[9];
    const float* gateb      = (const float*)d_in[10];
    const float* rms_scale  = (const float*)d_in[11];

    nop_kernel<<<1, 1>>>();
    nop_kernel<<<1, 1>>>();
    nop_kernel<<<1, 1>>>();
    dim3 grid1(NCH, B_);
    pass1_kernel<<<grid1, NT>>>(tok, prv, mask, embed, engram,
                                gate_logit, temp, salW, salb);
    pass2_kernel<<<B_, 512>>>(gateW, gateb, rms_scale, (float*)d_out);
}

// round 14
// speedup vs baseline: 1.1616x; 1.1616x over previous
#include <cuda_runtime.h>
#include <cuda_bf16.h>
#include <math.h>

// Problem constants
#define B_  64
#define T_  2048
#define O_  3
#define D_  512
#define M_  100000u
#define H_  4

// Tiling
#define NCH 16           // chunks of T per batch row
#define TCH (T_ / NCH)   // 128 timesteps per chunk  (== NT)
#define TW  8            // unmasked timesteps per tile
#define NT  128          // thread t owns dims [4t,4t+4); warp == head

// Chunk partial softmax state
__device__ float g_m[B_ * NCH * H_];
__device__ float g_s[B_ * NCH * H_];
__device__ float g_acc[B_ * NCH * D_];

__global__ __launch_bounds__(NT, 5)
void pass1_kernel(const int* __restrict__ tok,
                  const int* __restrict__ prv,
                  const int* __restrict__ mask,       // bool delivered as int32
                  const float* __restrict__ embed,
                  const float* __restrict__ engram,
                  const float* __restrict__ gate_logit,
                  const float* __restrict__ temp,
                  const float* __restrict__ salW,
                  const float* __restrict__ salb)
{
    const int b = blockIdx.y;
    const int c = blockIdx.x;
    const int t = threadIdx.x;          // 0..127
    const int h = t >> 5;               // warp index == head
    const int lane = t & 31;

    __shared__ unsigned int   stok[TCH + O_];
    __shared__ unsigned short sidx[TCH + TW];   // compacted unmasked local-t list
    __shared__ float spart[2][TW][H_][H_];      // [parity][j][warp][head]
    __shared__ int   scnt[H_], sbase[H_], snv;

    const int t0 = c * TCH;

    // Stage tokens
    for (int i = t; i < TCH + O_; i += NT) {
        int u = t0 - O_ + i;
        stok[i] = (u < 0) ? (unsigned)prv[b * O_ + (O_ + u)]
                          : (unsigned)tok[b * T_ + u];
    }

    // ---- Mask compaction: one ballot per warp (TCH == NT) ----
    int mvv = (mask[b * T_ + t0 + t] != 0);
    unsigned bal = __ballot_sync(0xffffffffu, mvv);
    if (lane == 0) scnt[h] = __popc(bal);
    __syncthreads();
    if (t == 0) {
        int run = 0;
        #pragma unroll
        for (int seg = 0; seg < H_; seg++) { sbase[seg] = run; run += scnt[seg]; }
        snv = run;
    }
    __syncthreads();
    {
        int off = sbase[h] + __popc(bal & ((1u << lane) - 1u));
        if (mvv) sidx[off] = (unsigned short)t;
    }
    const int nv = snv;
    if (t < TW) sidx[nv + t] = 0;               // pad with safe index
    __syncthreads();

    // Per-thread constants
    float4 gl = __ldg((const float4*)gate_logit + t);
    float4 g4;
    g4.x = 1.0f / (1.0f + __expf(-gl.x));
    g4.y = 1.0f / (1.0f + __expf(-gl.y));
    g4.z = 1.0f / (1.0f + __expf(-gl.z));
    g4.w = 1.0f / (1.0f + __expf(-gl.w));

    float4 Wr0 = __ldg((const float4*)salW + (t * 4 + 0));
    float4 Wr1 = __ldg((const float4*)salW + (t * 4 + 1));
    float4 Wr2 = __ldg((const float4*)salW + (t * 4 + 2));
    float4 Wr3 = __ldg((const float4*)salW + (t * 4 + 3));

    const float invT = 1.0f / (log1pf(__expf(temp[h])) + 0.3f);
    const float bias = salb[h];

    unsigned P0, P1, P2, P3;
    {
        unsigned x = 131u + (unsigned)h * 1009u;
        P0 = x; x = x * 31u + 1u;
        P1 = x; x = x * 31u + 1u;
        P2 = x; x = x * 31u + 1u;
        P3 = x;
    }

    float  m = -1e30f, s = 0.0f;
    float4 acc = make_float4(0.f, 0.f, 0.f, 0.f);

    for (int tt = 0; tt < nv; tt += TW) {
        const int pb = (tt / TW) & 1;

        // ---- Phase A: issue all engram gathers (L2-only); remember c0 for JIT embed ----
        float4 e[TW];
        unsigned c0s[TW];
        #pragma unroll
        for (int j = 0; j < TW; j++) {
            int li = sidx[tt + j];
            unsigned c0 = stok[li + 3];
            unsigned c1 = stok[li + 2];
            unsigned c2 = stok[li + 1];
            unsigned c3 = stok[li + 0];
            unsigned idx = (c0 * P0 + c1 * P1 + c2 * P2 + c3 * P3) % M_;
            c0s[j] = c0;
            e[j] = __ldcg((const float4*)(engram + (size_t)idx * D_) + t);
        }

        // ---- Phase B: x in regs (embed JIT from L1), logits via 11-shuffle reduction ----
        #pragma unroll
        for (int j = 0; j < TW; j++) {
            float4 bv = __ldg((const float4*)(embed + (size_t)c0s[j] * D_) + t);
            float4 x4;
            x4.x = fmaf(e[j].x, g4.x, bv.x);
            x4.y = fmaf(e[j].y, g4.y, bv.y);
            x4.z = fmaf(e[j].z, g4.z, bv.z);
            x4.w = fmaf(e[j].w, g4.w, bv.w);
            e[j] = x4;

            float p0 = fmaf(x4.x, Wr0.x, fmaf(x4.y, Wr1.x, fmaf(x4.z, Wr2.x, x4.w * Wr3.x)));
            float p1 = fmaf(x4.x, Wr0.y, fmaf(x4.y, Wr1.y, fmaf(x4.z, Wr2.y, x4.w * Wr3.y)));
            float p2 = fmaf(x4.x, Wr0.z, fmaf(x4.y, Wr1.z, fmaf(x4.z, Wr2.z, x4.w * Wr3.z)));
            float p3 = fmaf(x4.x, Wr0.w, fmaf(x4.y, Wr1.w, fmaf(x4.z, Wr2.w, x4.w * Wr3.w)));
            p0 += __shfl_xor_sync(0xffffffffu, p0, 16);
            p1 += __shfl_xor_sync(0xffffffffu, p1, 16);
            p2 += __shfl_xor_sync(0xffffffffu, p2, 16);
            p3 += __shfl_xor_sync(0xffffffffu, p3, 16);
            p0 += __shfl_xor_sync(0xffffffffu, p0, 8);
            p1 += __shfl_xor_sync(0xffffffffu, p1, 8);
            p2 += __shfl_xor_sync(0xffffffffu, p2, 8);
            p3 += __shfl_xor_sync(0xffffffffu, p3, 8);
            int oct = lane >> 3;
            float v = (oct == 0) ? p0 : (oct == 1) ? p1 : (oct == 2) ? p2 : p3;
            v += __shfl_xor_sync(0xffffffffu, v, 4);
            v += __shfl_xor_sync(0xffffffffu, v, 2);
            v += __shfl_xor_sync(0xffffffffu, v, 1);
            if ((lane & 7) == 0) spart[pb][j][h][oct] = v;
        }
        __syncthreads();

        // ---- Phase C: tile-level softmax update (short dependency chain) ----
        float l[TW]; float lm = -3e38f;
        #pragma unroll
        for (int j = 0; j < TW; j++) {
            float lg = spart[pb][j][0][h] + spart[pb][j][1][h]
                     + spart[pb][j][2][h] + spart[pb][j][3][h];
            l[j] = (tt + j < nv) ? (lg + bias) * invT : -3e38f;
            lm = fmaxf(lm, l[j]);
        }
        float nm = fmaxf(m, lm);
        float sc = __expf(m - nm);
        float ws = 0.0f; float w[TW];
        #pragma unroll
        for (int j = 0; j < TW; j++) {
            w[j] = (tt + j < nv) ? __expf(l[j] - nm) : 0.0f;
            ws += w[j];
        }
        s = fmaf(s, sc, ws);
        float ax = acc.x * sc, ay = acc.y * sc, az = acc.z * sc, aw = acc.w * sc;
        #pragma unroll
        for (int j = 0; j < TW; j++) {
            ax = fmaf(w[j], e[j].x, ax);
            ay = fmaf(w[j], e[j].y, ay);
            az = fmaf(w[j], e[j].z, az);
            aw = fmaf(w[j], e[j].w, aw);
        }
        acc.x = ax; acc.y = ay; acc.z = az; acc.w = aw;
        m = nm;
        // no barrier here: next tile writes the other spart parity
    }

    const int pi = (b * NCH + c);
    ((float4*)(g_acc + (size_t)pi * D_))[t] = acc;
    if (lane == 0) {
        g_m[pi * H_ + h] = m;
        g_s[pi * H_ + h] = s;
    }
}

__global__ __launch_bounds__(512)
void pass2_kernel(const float* __restrict__ gateW,
                  const float* __restrict__ gateb,
                  const float* __restrict__ rms_scale,
                  float* __restrict__ out)
{
    const int b = blockIdx.x;
    const int d = threadIdx.x;
    const int h = d >> 7;
    const int ld = d & 127;
    const int lane = d & 31;
    const int wid  = d >> 5;

    __shared__ float red_g[16];
    __shared__ float red_q[16];
    __shared__ float sgl[H_];
    __shared__ float ssq_sh;

    float m = -1e30f;
    #pragma unroll
    for (int c = 0; c < NCH; c++)
        m = fmaxf(m, g_m[(b * NCH + c) * H_ + h]);
    float s = 0.0f, a = 0.0f;
    #pragma unroll
    for (int c = 0; c < NCH; c++) {
        float mc = g_m[(b * NCH + c) * H_ + h];
        float sc = __expf(mc - m);
        s += g_s[(b * NCH + c) * H_ + h] * sc;
        a += g_acc[(b * NCH + c) * D_ + d] * sc;
    }
    float wv = a / (s + 1e-6f);

    float p = wv * gateW[ld];
    #pragma unroll
    for (int o = 16; o > 0; o >>= 1) p += __shfl_xor_sync(0xffffffffu, p, o);
    if (lane == 0) red_g[wid] = p;

    float q = wv * wv;
    #pragma unroll
    for (int o = 16; o > 0; o >>= 1) q += __shfl_xor_sync(0xffffffffu, q, o);
    if (lane == 0) red_q[wid] = q;
    __syncthreads();

    if (d < H_) {
        sgl[d] = red_g[d * 4] + red_g[d * 4 + 1] + red_g[d * 4 + 2] + red_g[d * 4 + 3] + gateb[0];
    }
    if (d == 0) {
        float qq = 0.0f;
        #pragma unroll
        for (int i = 0; i < 16; i++) qq += red_q[i];
        ssq_sh = qq;
    }
    __syncthreads();

    float valid = (s > 0.0f) ? 1.0f : 0.0f;
    float u = valid / (1.0f + __expf(-sgl[h]));
    float rms = sqrtf(ssq_sh * (1.0f / (float)D_) + 1e-6f);

    out[b * (2 * D_) + d]       = wv / rms * rms_scale[d];
    out[b * (2 * D_) + D_ + d]  = u;
}

// Profiler captures absolute launch #3 (0-based); three nops put pass1 there.
__global__ void nop_kernel() {}

extern "C" void kernel_launch(void* const* d_in, const int* in_sizes, int n_in,
                              void* d_out, int out_size)
{
    const int*   tok        = (const int*)d_in[0];
    const int*   prv        = (const int*)d_in[1];
    const int*   mask       = (const int*)d_in[2];
    const float* embed      = (const float*)d_in[3];
    const float* engram     = (const float*)d_in[4];
    const float* gate_logit = (const float*)d_in[5];
    const float* temp       = (const float*)d_in[6];
    const float* salW       = (const float*)d_in[7];
    const float* salb       = (const float*)d_in[8];
    const float* gateW      = (const float*)d_in[9];
    const float* gateb      = (const float*)d_in[10];
    const float* rms_scale  = (const float*)d_in[11];

    nop_kernel<<<1, 1>>>();
    nop_kernel<<<1, 1>>>();
    nop_kernel<<<1, 1>>>();
    dim3 grid1(NCH, B_);
    pass1_kernel<<<grid1, NT>>>(tok, prv, mask, embed, engram,
                                gate_logit, temp, salW, salb);
    pass2_kernel<<<B_, 512>>>(gateW, gateb, rms_scale, (float*)d_out);
}

// round 15
// speedup vs baseline: 1.7139x; 1.4755x over previous
#include <cuda_runtime.h>
#include <cuda_bf16.h>
#include <math.h>

// Problem constants
#define B_  64
#define T_  2048
#define O_  3
#define D_  512
#define M_  100000u
#define H_  4

// Tiling
#define NCH 8            // chunks of T per batch row (grid = 512 CTAs = single wave @ occ 4)
#define TCH (T_ / NCH)   // 256 timesteps per chunk
#define TW  8            // unmasked timesteps per tile
#define NT  128          // thread t owns dims [4t,4t+4); warp == head

// Chunk partial softmax state + completion counters
__device__ float g_m[B_ * NCH * H_];
__device__ float g_s[B_ * NCH * H_];
__device__ float g_acc[B_ * NCH * D_];
__device__ int   g_cnt[B_];            // zero-init; self-resetting each run

__global__ __launch_bounds__(NT, 4)
void fused_kernel(const int* __restrict__ tok,
                  const int* __restrict__ prv,
                  const int* __restrict__ mask,       // bool delivered as int32
                  const float* __restrict__ embed,
                  const float* __restrict__ engram,
                  const float* __restrict__ gate_logit,
                  const float* __restrict__ temp,
                  const float* __restrict__ salW,
                  const float* __restrict__ salb,
                  const float* __restrict__ gateW,
                  const float* __restrict__ gateb,
                  const float* __restrict__ rms_scale,
                  float* __restrict__ out)
{
    const int b = blockIdx.y;
    const int c = blockIdx.x;
    const int t = threadIdx.x;          // 0..127
    const int h = t >> 5;               // warp index == head
    const int lane = t & 31;

    __shared__ unsigned int   stok[TCH + O_];
    __shared__ unsigned short sidx[TCH + TW];   // compacted unmasked local-t list
    __shared__ float spart[2][TW][H_][H_];      // [parity][j][warp][head]
    __shared__ int   scnt[8], sbase[8], snv;
    __shared__ float sgl[H_], ssq[H_];
    __shared__ int   s_last;

    const int t0 = c * TCH;

    // Stage tokens
    for (int i = t; i < TCH + O_; i += NT) {
        int u = t0 - O_ + i;
        stok[i] = (u < 0) ? (unsigned)prv[b * O_ + (O_ + u)]
                          : (unsigned)tok[b * T_ + u];
    }

    // ---- Mask compaction: ballot + scan (2 segments per warp) ----
    unsigned bal[2]; int mv[2];
    #pragma unroll
    for (int k = 0; k < 2; k++) {
        int seg = h * 2 + k;
        mv[k]  = (mask[b * T_ + t0 + seg * 32 + lane] != 0);
        bal[k] = __ballot_sync(0xffffffffu, mv[k]);
        if (lane == 0) scnt[seg] = __popc(bal[k]);
    }
    __syncthreads();
    if (t == 0) {
        int run = 0;
        #pragma unroll
        for (int seg = 0; seg < 8; seg++) { sbase[seg] = run; run += scnt[seg]; }
        snv = run;
    }
    __syncthreads();
    #pragma unroll
    for (int k = 0; k < 2; k++) {
        int seg = h * 2 + k;
        int off = sbase[seg] + __popc(bal[k] & ((1u << lane) - 1u));
        if (mv[k]) sidx[off] = (unsigned short)(seg * 32 + lane);
    }
    const int nv = snv;
    if (t < TW) sidx[nv + t] = 0;               // pad with safe index
    __syncthreads();

    // Per-thread constants
    float4 gl = __ldg((const float4*)gate_logit + t);
    float4 g4;
    g4.x = 1.0f / (1.0f + __expf(-gl.x));
    g4.y = 1.0f / (1.0f + __expf(-gl.y));
    g4.z = 1.0f / (1.0f + __expf(-gl.z));
    g4.w = 1.0f / (1.0f + __expf(-gl.w));

    float4 Wr0 = __ldg((const float4*)salW + (t * 4 + 0));
    float4 Wr1 = __ldg((const float4*)salW + (t * 4 + 1));
    float4 Wr2 = __ldg((const float4*)salW + (t * 4 + 2));
    float4 Wr3 = __ldg((const float4*)salW + (t * 4 + 3));

    const float invT = 1.0f / (log1pf(__expf(temp[h])) + 0.3f);
    const float bias = salb[h];

    unsigned P0, P1, P2, P3;
    {
        unsigned x = 131u + (unsigned)h * 1009u;
        P0 = x; x = x * 31u + 1u;
        P1 = x; x = x * 31u + 1u;
        P2 = x; x = x * 31u + 1u;
        P3 = x;
    }

    float  m = -1e30f, s = 0.0f;
    float4 acc = make_float4(0.f, 0.f, 0.f, 0.f);

    for (int tt = 0; tt < nv; tt += TW) {
        const int pb = (tt / TW) & 1;

        // ---- Phase A: batch-issue engram (L2-only) + embed (L1) loads ----
        float4 e[TW], bv[TW];
        #pragma unroll
        for (int j = 0; j < TW; j++) {
            int li = sidx[tt + j];
            unsigned c0 = stok[li + 3];
            unsigned c1 = stok[li + 2];
            unsigned c2 = stok[li + 1];
            unsigned c3 = stok[li + 0];
            unsigned idx = (c0 * P0 + c1 * P1 + c2 * P2 + c3 * P3) % M_;
            e[j]  = __ldcg((const float4*)(engram + (size_t)idx * D_) + t);
            bv[j] = __ldg ((const float4*)(embed  + (size_t)c0  * D_) + t);
        }

        // ---- Phase B: x in regs, logits via 9-shuffle role-split reduction ----
        #pragma unroll
        for (int j = 0; j < TW; j++) {
            float4 x4;
            x4.x = fmaf(e[j].x, g4.x, bv[j].x);
            x4.y = fmaf(e[j].y, g4.y, bv[j].y);
            x4.z = fmaf(e[j].z, g4.z, bv[j].z);
            x4.w = fmaf(e[j].w, g4.w, bv[j].w);
            e[j] = x4;

            float p0 = fmaf(x4.x, Wr0.x, fmaf(x4.y, Wr1.x, fmaf(x4.z, Wr2.x, x4.w * Wr3.x)));
            float p1 = fmaf(x4.x, Wr0.y, fmaf(x4.y, Wr1.y, fmaf(x4.z, Wr2.y, x4.w * Wr3.y)));
            float p2 = fmaf(x4.x, Wr0.z, fmaf(x4.y, Wr1.z, fmaf(x4.z, Wr2.z, x4.w * Wr3.z)));
            float p3 = fmaf(x4.x, Wr0.w, fmaf(x4.y, Wr1.w, fmaf(x4.z, Wr2.w, x4.w * Wr3.w)));
            // role-split: offset 16 (4 shuffles)
            float t0s = __shfl_xor_sync(0xffffffffu, p0, 16);
            float t1s = __shfl_xor_sync(0xffffffffu, p1, 16);
            float t2s = __shfl_xor_sync(0xffffffffu, p2, 16);
            float t3s = __shfl_xor_sync(0xffffffffu, p3, 16);
            bool hi16 = (lane & 16) != 0;
            float q0 = hi16 ? (p2 + t2s) : (p0 + t0s);
            float q1 = hi16 ? (p3 + t3s) : (p1 + t1s);
            // offset 8 (2 shuffles)
            float u0 = __shfl_xor_sync(0xffffffffu, q0, 8);
            float u1 = __shfl_xor_sync(0xffffffffu, q1, 8);
            float v = (lane & 8) ? (q1 + u1) : (q0 + u0);
            // finish within octet (3 shuffles); octet o holds head o
            v += __shfl_xor_sync(0xffffffffu, v, 4);
            v += __shfl_xor_sync(0xffffffffu, v, 2);
            v += __shfl_xor_sync(0xffffffffu, v, 1);
            if ((lane & 7) == 0) spart[pb][j][h][lane >> 3] = v;
        }
        __syncthreads();

        // ---- Phase C: tile-level softmax update ----
        float l[TW]; float lm = -3e38f;
        #pragma unroll
        for (int j = 0; j < TW; j++) {
            float lg = spart[pb][j][0][h] + spart[pb][j][1][h]
                     + spart[pb][j][2][h] + spart[pb][j][3][h];
            l[j] = (tt + j < nv) ? (lg + bias) * invT : -3e38f;
            lm = fmaxf(lm, l[j]);
        }
        float nm = fmaxf(m, lm);
        float sc = __expf(m - nm);
        float ws = 0.0f; float w[TW];
        #pragma unroll
        for (int j = 0; j < TW; j++) {
            w[j] = (tt + j < nv) ? __expf(l[j] - nm) : 0.0f;
            ws += w[j];
        }
        s = fmaf(s, sc, ws);
        float ax = acc.x * sc, ay = acc.y * sc, az = acc.z * sc, aw = acc.w * sc;
        #pragma unroll
        for (int j = 0; j < TW; j++) {
            ax = fmaf(w[j], e[j].x, ax);
            ay = fmaf(w[j], e[j].y, ay);
            az = fmaf(w[j], e[j].z, az);
            aw = fmaf(w[j], e[j].w, aw);
        }
        acc.x = ax; acc.y = ay; acc.z = az; acc.w = aw;
        m = nm;
        // no second barrier: next tile writes the other spart parity
    }

    // ---- Publish chunk partials ----
    const int pi = (b * NCH + c);
    ((float4*)(g_acc + (size_t)pi * D_))[t] = acc;
    if (lane == 0) {
        g_m[pi * H_ + h] = m;
        g_s[pi * H_ + h] = s;
    }
    __threadfence();
    if (t == 0) s_last = (atomicAdd(&g_cnt[b], 1) == NCH - 1);
    __syncthreads();
    if (!s_last) return;

    // ---- Last CTA for this b: merge + epilogue (replaces pass2) ----
    if (t == 0) g_cnt[b] = 0;   // self-reset for graph replay determinism

    float mm = -1e30f;
    #pragma unroll
    for (int cc = 0; cc < NCH; cc++)
        mm = fmaxf(mm, __ldcg(&g_m[(b * NCH + cc) * H_ + h]));
    float  ss = 0.0f;
    float4 av = make_float4(0.f, 0.f, 0.f, 0.f);
    #pragma unroll
    for (int cc = 0; cc < NCH; cc++) {
        float mc = __ldcg(&g_m[(b * NCH + cc) * H_ + h]);
        float sc = __expf(mc - mm);
        ss += __ldcg(&g_s[(b * NCH + cc) * H_ + h]) * sc;
        float4 ga = __ldcg((const float4*)(g_acc + (size_t)(b * NCH + cc) * D_) + t);
        av.x = fmaf(ga.x, sc, av.x);
        av.y = fmaf(ga.y, sc, av.y);
        av.z = fmaf(ga.z, sc, av.z);
        av.w = fmaf(ga.w, sc, av.w);
    }
    float inv_s = 1.0f / (ss + 1e-6f);
    float4 wv;
    wv.x = av.x * inv_s; wv.y = av.y * inv_s;
    wv.z = av.z * inv_s; wv.w = av.w * inv_s;

    // per-head gate logit: dot(wv[h,:], gateW) — thread's 4 dims are lane*4..lane*4+3 within head
    float4 gw = __ldg((const float4*)gateW + lane);
    float p = fmaf(wv.x, gw.x, fmaf(wv.y, gw.y, fmaf(wv.z, gw.z, wv.w * gw.w)));
    float q = fmaf(wv.x, wv.x, fmaf(wv.y, wv.y, fmaf(wv.z, wv.z, wv.w * wv.w)));
    #pragma unroll
    for (int o = 16; o > 0; o >>= 1) {
        p += __shfl_xor_sync(0xffffffffu, p, o);
        q += __shfl_xor_sync(0xffffffffu, q, o);
    }
    if (lane == 0) { sgl[h] = p; ssq[h] = q; }
    __syncthreads();

    float gate_l = sgl[h] + gateb[0];
    float sumsq  = ssq[0] + ssq[1] + ssq[2] + ssq[3];
    float valid  = (ss > 0.0f) ? 1.0f : 0.0f;
    float u      = valid / (1.0f + __expf(-gate_l));
    float inv_rms = rsqrtf(sumsq * (1.0f / (float)D_) + 1e-6f);

    float4 rs = __ldg((const float4*)rms_scale + t);
    float4 o1;
    o1.x = wv.x * inv_rms * rs.x;
    o1.y = wv.y * inv_rms * rs.y;
    o1.z = wv.z * inv_rms * rs.z;
    o1.w = wv.w * inv_rms * rs.w;
    ((float4*)(out + b * (2 * D_)))[t] = o1;
    ((float4*)(out + b * (2 * D_) + D_))[t] = make_float4(u, u, u, u);
}

extern "C" void kernel_launch(void* const* d_in, const int* in_sizes, int n_in,
                              void* d_out, int out_size)
{
    const int*   tok        = (const int*)d_in[0];
    const int*   prv        = (const int*)d_in[1];
    const int*   mask       = (const int*)d_in[2];
    const float* embed      = (const float*)d_in[3];
    const float* engram     = (const float*)d_in[4];
    const float* gate_logit = (const float*)d_in[5];
    const float* temp       = (const float*)d_in[6];
    const float* salW       = (const float*)d_in[7];
    const float* salb       = (const float*)d_in[8];
    const float* gateW      = (const float*)d_in[9];
    const float* gateb      = (const float*)d_in[10];
    const float* rms_scale  = (const float*)d_in[11];

    dim3 grid(NCH, B_);
    fused_kernel<<<grid, NT>>>(tok, prv, mask, embed, engram,
                               gate_logit, temp, salW, salb,
                               gateW, gateb, rms_scale, (float*)d_out);
}